// round 16
// baseline (speedup 1.0000x reference)
#include <cuda_runtime.h>
#include <cuda_fp16.h>
#include <math.h>
#include <stdint.h>

// Problem constants: B=4, S=2048, N_EMBD=1024, E=8, K=2, D_FF=4096
#define T_TOK 8192
#define D_IN  1024
#define D_FF  4096
#define NE    8

// ---------------------------------------------------------------------------
// Scratch (__device__ globals only)
// ---------------------------------------------------------------------------
__device__ int      g_cnt[NE];
__device__ int      g_fill[NE];
__device__ int      g_off[NE];
__device__ int      g_top[T_TOK * 2];
__device__ float    g_wt[T_TOK * 2];
__device__ int      g_tok[T_TOK * 2];
__device__ float    g_pw[T_TOK * 2];

// fp16 operand planes (single-plane, rounded)
__device__ __half g_xf [(size_t)T_TOK * D_IN];
__device__ __half g_w1f[(size_t)NE * D_IN * D_FF];
__device__ __half g_w2f[(size_t)NE * D_FF * D_IN];
__device__ __half g_hf [(size_t)T_TOK * 2 * D_FF];   // hidden acts fp16 (134 MB)

// ---------------------------------------------------------------------------
// Portable PTX helpers (sm_80+ only: mma.sync, ldmatrix, cp.async)
// ---------------------------------------------------------------------------
__device__ __forceinline__ uint32_t smem_u32(const void* p) {
    uint32_t a;
    asm("{ .reg .u64 t; cvta.to.shared.u64 t, %1; cvt.u32.u64 %0, t; }"
        : "=r"(a) : "l"(p));
    return a;
}
__device__ __forceinline__ void ldsm4(uint32_t* r, uint32_t addr) {
    asm volatile("ldmatrix.sync.aligned.m8n8.x4.shared.b16 {%0,%1,%2,%3}, [%4];"
        : "=r"(r[0]), "=r"(r[1]), "=r"(r[2]), "=r"(r[3]) : "r"(addr));
}
__device__ __forceinline__ void ldsm4t(uint32_t* r, uint32_t addr) {
    asm volatile("ldmatrix.sync.aligned.m8n8.x4.trans.shared.b16 {%0,%1,%2,%3}, [%4];"
        : "=r"(r[0]), "=r"(r[1]), "=r"(r[2]), "=r"(r[3]) : "r"(addr));
}
__device__ __forceinline__ void mma16816(float* d, const uint32_t* a,
                                         uint32_t b0, uint32_t b1) {
    asm volatile(
        "mma.sync.aligned.m16n8k16.row.col.f32.f16.f16.f32 "
        "{%0,%1,%2,%3}, {%4,%5,%6,%7}, {%8,%9}, {%0,%1,%2,%3};"
        : "+f"(d[0]), "+f"(d[1]), "+f"(d[2]), "+f"(d[3])
        : "r"(a[0]), "r"(a[1]), "r"(a[2]), "r"(a[3]), "r"(b0), "r"(b1));
}
__device__ __forceinline__ void cp16(uint32_t dst, const void* src) {
    asm volatile("cp.async.cg.shared.global [%0], [%1], 16;"
                 :: "r"(dst), "l"(src) : "memory");
}
__device__ __forceinline__ void cp_commit() {
    asm volatile("cp.async.commit_group;" ::: "memory");
}
template<int N> __device__ __forceinline__ void cp_wait() {
    asm volatile("cp.async.wait_group %0;" :: "n"(N) : "memory");
}

// fp16 round of float4 -> packed 2x(2xfp16)
__device__ __forceinline__ uint2 f16_round4(float4 v) {
    uint2 r;
    __half2 p0 = __floats2half2_rn(v.x, v.y);
    __half2 p1 = __floats2half2_rn(v.z, v.w);
    r.x = *(uint32_t*)&p0;
    r.y = *(uint32_t*)&p1;
    return r;
}

// ---------------------------------------------------------------------------
// SMEM: THREE 32 KB stages; each stage = two 16 KB sub-blocks (32-k each):
//   sub: [0,8192)     A : 128 rows x 32 fp16 (64B rows, swizzled)
//        [8192,16384) B : 4 subtiles [32k x 32n] (64B rows, swizzled)
// Swizzle: chunk' = chunk ^ ((row>>1)&3)  (16B chunks, 4 per 64B row)
// ---------------------------------------------------------------------------
#define NSTAGE 3
#define SUB_BYTES 16384
#define BUF_BYTES 32768
#define SMEM_BYTES (NSTAGE * BUF_BYTES)   // 96 KB -> 2 CTAs/SM (192 KB)
#define OFF_A 0
#define OFF_B 8192

__device__ __forceinline__ int swz(int row, int chunk) {
    return row * 64 + ((chunk ^ ((row >> 1) & 3)) << 4);
}

// ---------------------------------------------------------------------------
// fp16 HMMA GEMM: 3-stage ring, 1 barrier/stage, INTRA-STAGE rolling prefetch:
//  - q0 fragments loaded after the barrier that published the stage (legal)
//  - B double-buffered by quarter parity, prefetched one quarter ahead
//  - a[i] reloaded in place right after its last use (q<3)
//  - cp_wait<1> + __syncthreads at END of iteration publishes stage ch+1 to
//    all threads BEFORE any thread reads it (fixes the R14 visibility race:
//    cp_wait only covers the calling thread's copies).
//  GATHER=true : A = g_xf[g_tok], epilogue relu+bias -> g_hf (fp16)   K=1024
//  GATHER=false: A = g_hf,        epilogue bias, *w -> atomicAdd out  K=4096
// CTA tile 128x128, K-stage 64 (4 quarters of 16k), 256 threads, 8 warps.
// ---------------------------------------------------------------------------
template<int K_TOTAL, int B_STRIDE, bool GATHER>
__global__ __launch_bounds__(256, 2)
void moe_mma_kernel(const __half* __restrict__ Bw,
                    const float* __restrict__ bias,
                    float* __restrict__ out) {
    const int e   = blockIdx.z;
    const int cnt = g_cnt[e];
    const int m0  = blockIdx.y * 128;
    if (m0 >= cnt) return;
    const int n0   = blockIdx.x * 128;
    const int base = g_off[e];

    extern __shared__ char smem[];
    const uint32_t sb = smem_u32(smem);
    const int t    = threadIdx.x;
    const int lane = t & 31;
    const int wid  = t >> 5;
    const int wm   = wid >> 2;     // 0..1
    const int wn   = wid & 3;      // 0..3

    // ---- cp.async staging assignments ----------------------------------
    const int rowA = t >> 1;
    const int colA = (t & 1) * 16;
    const int cA0  = (t & 1) * 2;
    const __half* a_row;
    {
        int m = min(m0 + rowA, cnt - 1);
        if (GATHER) a_row = g_xf + (size_t)g_tok[base + m] * D_IN;
        else        a_row = g_hf + (size_t)(base + m) * D_FF;
    }
    const int kB   = t >> 3;
    const int nb   = (t & 7) * 16;
    const int bsub = nb >> 5;
    const int cB0  = ((nb & 31) >> 3);
    const __half* b_p = Bw + (size_t)e * K_TOTAL * B_STRIDE + n0 + nb;

    const int NCH = K_TOTAL / 64;

    // issue stage ch2 into ring slot; empty commit past end
    auto issue_stage = [&](int ch2, int slot) {
        if (ch2 < NCH) {
            const int k0 = ch2 * 64;
            const uint32_t s = sb + slot * BUF_BYTES;
#pragma unroll
            for (int sub = 0; sub < 2; sub++) {
                const uint32_t ss = s + sub * SUB_BYTES;
                const int k0s = k0 + 32 * sub;
                uint32_t d0 = ss + OFF_A + swz(rowA, cA0);
                uint32_t d1 = ss + OFF_A + swz(rowA, cA0 + 1);
                cp16(d0, a_row + k0s + colA);
                cp16(d1, a_row + k0s + colA + 8);
                uint32_t e0 = ss + OFF_B + bsub * 2048 + swz(kB, cB0);
                uint32_t e1 = ss + OFF_B + bsub * 2048 + swz(kB, cB0 + 1);
                const __half* sB = b_p + (size_t)(k0s + kB) * B_STRIDE;
                cp16(e0, sB);
                cp16(e1, sB + 8);
            }
        }
        cp_commit();   // uniform group accounting
    };

    float acc[4][4][4];
#pragma unroll
    for (int i = 0; i < 4; i++)
#pragma unroll
        for (int j = 0; j < 4; j++)
#pragma unroll
            for (int r = 0; r < 4; r++) acc[i][j][r] = 0.f;

    const int ml   = lane & 15;
    const int chhi = lane >> 4;

    // fragment loaders (quarter q of a slot: sub = q>>1, ks = q&1)
    auto ldA_i = [&](int slot, int q, int i, uint32_t* dst) {
        const uint32_t ss = sb + slot * BUF_BYTES + (q >> 1) * SUB_BYTES;
        int m = wm * 64 + i * 16 + ml;
        int cc = ((q & 1) * 2 + chhi) ^ ((m >> 1) & 3);
        ldsm4(dst, ss + OFF_A + m * 64 + cc * 16);
    };
    auto ldB_q = [&](int slot, int q, uint32_t (*dst)[4]) {
        const uint32_t ss = sb + slot * BUF_BYTES + (q >> 1) * SUB_BYTES;
        int k = (q & 1) * 16 + ml;
#pragma unroll
        for (int p = 0; p < 2; p++) {
            int cc = (p * 2 + chhi) ^ ((k >> 1) & 3);
            ldsm4t(dst[p], ss + OFF_B + wn * 2048 + k * 64 + cc * 16);
        }
    };

    uint32_t a[4][4];        // A fragments, rotated in place
    uint32_t bq[2][2][4];    // B fragments, double-buffered by quarter parity

    // ---- prologue: publish stage 0 to ALL threads -----------------------
    issue_stage(0, 0);
    issue_stage(1, 1);
    cp_wait<1>();            // own part of group 0 done
    __syncthreads();         // everyone's part of stage 0 done & visible

    int s_mma = 0, s_iss = 2;
    for (int ch = 0; ch < NCH; ch++) {
        issue_stage(ch + 2, s_iss);    // overwrite stage ch-1's slot (reads closed
                                       // by the barrier at end of iter ch-1)
        // q0 fragment loads: stage s_mma is published (end-of-prev-iter barrier)
        ldB_q(s_mma, 0, bq[0]);
#pragma unroll
        for (int i = 0; i < 4; i++) ldA_i(s_mma, 0, i, a[i]);

#pragma unroll
        for (int q = 0; q < 4; q++) {
            const int qp = q & 1;
            if (q < 3) ldB_q(s_mma, q + 1, bq[qp ^ 1]);   // next-quarter B
#pragma unroll
            for (int i = 0; i < 4; i++) {
#pragma unroll
                for (int j = 0; j < 4; j++)
                    mma16816(acc[i][j], a[i],
                             bq[qp][j >> 1][(j & 1) * 2],
                             bq[qp][j >> 1][(j & 1) * 2 + 1]);
                // a[i] dead now: reload in place for next quarter (intra-stage)
                if (q < 3) ldA_i(s_mma, q + 1, i, a[i]);
            }
        }

        cp_wait<1>();        // own part of group ch+1 done (issued 0..ch+2)
        __syncthreads();     // publish stage ch+1; close reads of stage ch
        s_mma = (s_mma + 1 == NSTAGE) ? 0 : s_mma + 1;
        s_iss = (s_iss + 1 == NSTAGE) ? 0 : s_iss + 1;
    }

    // ---- epilogue -------------------------------------------------------
    const float* be = bias + (size_t)e * B_STRIDE;
#pragma unroll
    for (int i = 0; i < 4; i++) {
        int mA = m0 + wm * 64 + i * 16 + (lane >> 2);
#pragma unroll
        for (int half = 0; half < 2; half++) {     // rows mA and mA+8
            int m = mA + half * 8;
            if (m >= cnt) continue;
            size_t hrow = 0;
            float* op = nullptr;
            float  rw = 0.f;
            if (GATHER) {
                hrow = (size_t)(base + m) * D_FF;
            } else {
                op = out + (size_t)g_tok[base + m] * D_IN;
                rw = g_pw[base + m];
            }
#pragma unroll
            for (int j = 0; j < 4; j++) {
                int n = n0 + wn * 32 + j * 8 + (lane & 3) * 2;
                float v0 = acc[i][j][half * 2 + 0] + be[n];
                float v1 = acc[i][j][half * 2 + 1] + be[n + 1];
                if (GATHER) {
                    __half2 p = __floats2half2_rn(fmaxf(v0, 0.f), fmaxf(v1, 0.f));
                    *(uint32_t*)(g_hf + hrow + n) = *(uint32_t*)&p;
                } else {
                    atomicAdd(&op[n],     rw * v0);
                    atomicAdd(&op[n + 1], rw * v1);
                }
            }
        }
    }
}

// ---------------------------------------------------------------------------
// prep: zero routing counters + ALL fp32->fp16 conversions in ONE launch
// ---------------------------------------------------------------------------
__global__ void prep_kernel(const float* __restrict__ x,
                            const float* __restrict__ W1,
                            const float* __restrict__ W2) {
    if (blockIdx.x == 0 && threadIdx.x < NE) {
        g_cnt[threadIdx.x] = 0;
        g_fill[threadIdx.x] = 0;
    }
    const int N_X = (T_TOK * D_IN) / 4;
    const int N_W = (NE * D_IN * D_FF) / 4;
    const int stride = gridDim.x * blockDim.x;
    const int i0 = blockIdx.x * blockDim.x + threadIdx.x;
    for (int i = i0; i < N_X; i += stride)
        ((uint2*)g_xf)[i] = f16_round4(((const float4*)x)[i]);
    for (int i = i0; i < N_W; i += stride)
        ((uint2*)g_w1f)[i] = f16_round4(((const float4*)W1)[i]);
    for (int i = i0; i < N_W; i += stride)
        ((uint2*)g_w2f)[i] = f16_round4(((const float4*)W2)[i]);
}

// ---------------------------------------------------------------------------
// Router (unchanged, proven)
// ---------------------------------------------------------------------------
__global__ void router_kernel(const float* __restrict__ x,
                              const float* __restrict__ Wr,
                              const float* __restrict__ br) {
    int gw   = (blockIdx.x * blockDim.x + threadIdx.x) >> 5;
    int lane = threadIdx.x & 31;
    if (gw >= T_TOK) return;

    const float* xr = x + (size_t)gw * D_IN;
    float acc[NE];
#pragma unroll
    for (int e = 0; e < NE; e++) acc[e] = 0.f;

    for (int d = lane; d < D_IN; d += 32) {
        float xv = xr[d];
        float4 a = *(const float4*)(Wr + d * NE);
        float4 b = *(const float4*)(Wr + d * NE + 4);
        acc[0] += xv * a.x; acc[1] += xv * a.y; acc[2] += xv * a.z; acc[3] += xv * a.w;
        acc[4] += xv * b.x; acc[5] += xv * b.y; acc[6] += xv * b.z; acc[7] += xv * b.w;
    }
#pragma unroll
    for (int e = 0; e < NE; e++) {
#pragma unroll
        for (int o = 16; o > 0; o >>= 1)
            acc[e] += __shfl_xor_sync(0xffffffffu, acc[e], o);
    }
    if (lane == 0) {
        float lg[NE];
#pragma unroll
        for (int e = 0; e < NE; e++) lg[e] = acc[e] + br[e];
        int i0 = 0;
#pragma unroll
        for (int e = 1; e < NE; e++) if (lg[e] > lg[i0]) i0 = e;
        int i1 = (i0 == 0) ? 1 : 0;
#pragma unroll
        for (int e = 0; e < NE; e++) if (e != i0 && lg[e] > lg[i1]) i1 = e;
        float ex  = expf(lg[i1] - lg[i0]);
        float inv = 1.0f / (1.0f + ex);
        g_top[2 * gw + 0] = i0;  g_top[2 * gw + 1] = i1;
        g_wt [2 * gw + 0] = inv; g_wt [2 * gw + 1] = ex * inv;
        atomicAdd(&g_cnt[i0], 1);
        atomicAdd(&g_cnt[i1], 1);
    }
}

// ---------------------------------------------------------------------------
// scan + fill fused: single block (thread 0 scans, then all threads pack)
// ---------------------------------------------------------------------------
__global__ void scanfill_kernel() {
    if (threadIdx.x == 0) {
        int s = 0;
        for (int e = 0; e < NE; e++) { g_off[e] = s; s += g_cnt[e]; }
    }
    __syncthreads();
    for (int t = threadIdx.x; t < T_TOK; t += blockDim.x) {
#pragma unroll
        for (int s = 0; s < 2; s++) {
            int e = g_top[2 * t + s];
            int p = g_off[e] + atomicAdd(&g_fill[e], 1);
            g_tok[p] = t;
            g_pw[p]  = g_wt[2 * t + s];
        }
    }
}

// ---------------------------------------------------------------------------
// launch: memset(1) prep(2) router(3) scanfill(4) FFN1(5=profiled) FFN2(6)
// ---------------------------------------------------------------------------
extern "C" void kernel_launch(void* const* d_in, const int* in_sizes, int n_in,
                              void* d_out, int out_size) {
    const float* x   = (const float*)d_in[0];
    const float* Wr  = (const float*)d_in[1];
    const float* br  = (const float*)d_in[2];
    const float* W1  = (const float*)d_in[3];
    const float* b1  = (const float*)d_in[4];
    const float* W2  = (const float*)d_in[5];
    const float* b2  = (const float*)d_in[6];
    float*       out = (float*)d_out;

    cudaFuncSetAttribute(moe_mma_kernel<1024, 4096, true>,
                         cudaFuncAttributeMaxDynamicSharedMemorySize, SMEM_BYTES);
    cudaFuncSetAttribute(moe_mma_kernel<4096, 1024, false>,
                         cudaFuncAttributeMaxDynamicSharedMemorySize, SMEM_BYTES);

    __half *w1f, *w2f;
    cudaGetSymbolAddress((void**)&w1f, g_w1f);
    cudaGetSymbolAddress((void**)&w2f, g_w2f);

    cudaMemsetAsync(out, 0, (size_t)out_size * sizeof(float));
    prep_kernel<<<2048, 256>>>(x, W1, W2);
    router_kernel<<<T_TOK / 8, 256>>>(x, Wr, br);
    scanfill_kernel<<<1, 256>>>();

    // FFN1: h = relu(x_g @ W1 + b1) -> g_hf; K=1024
    moe_mma_kernel<1024, 4096, true>
        <<<dim3(D_FF / 128, T_TOK / 128, NE), 256, SMEM_BYTES>>>(w1f, b1, out);
    // FFN2: out += w * (h @ W2 + b2); K=4096
    moe_mma_kernel<4096, 1024, false>
        <<<dim3(D_IN / 128, T_TOK / 128, NE), 256, SMEM_BYTES>>>(w2f, b2, out);
}